// round 8
// baseline (speedup 1.0000x reference)
#include <cuda_runtime.h>
#include <cstdint>

// Real solid harmonics, max_l = 6, factored form:
//   out[l(l+1)+m] = ns[l(l+1)+m] * P_{l,|m|}(z, w) * (A_|m| or B_|m|)
// with w = x^2+y^2, A_m + i B_m = (x + i y)^m.
// Non-persistent CTAs, 256-point tile staged in 50KB dynamic smem,
// one TMA bulk store per CTA; overlap comes from CTA oversubscription.

#define BLK 256
#define NOUT 49
#define TILE_FLOATS (BLK * NOUT)
#define TILE_BYTES (TILE_FLOATS * 4)   // 50176, multiple of 16

__device__ __forceinline__ uint32_t smem_u32(const void* p) {
    uint32_t a;
    asm("{ .reg .u64 t; cvta.to.shared.u64 t, %1; cvt.u32.u64 %0, t; }"
        : "=r"(a) : "l"(p));
    return a;
}

__device__ __forceinline__ void compute_point(
    float x, float y, float z, const float* __restrict__ sns, float* __restrict__ o)
{
    const float w  = x * x + y * y;
    const float z2 = z * z;
    const float z4 = z2 * z2;
    const float z6 = z4 * z2;
    const float w2 = w * w;
    const float w3 = w2 * w;

    // m = 0
    o[0]  = sns[0];
    o[2]  = sns[2]  * z;
    o[6]  = sns[6]  * (z2 - 0.5f * w);
    o[12] = sns[12] * (z * (z2 - 1.5f * w));
    o[20] = sns[20] * (z4 - 3.f * w * z2 + 0.375f * w2);
    o[30] = sns[30] * (z * (z4 - 5.f * w * z2 + 1.875f * w2));
    o[42] = sns[42] * (z6 - 7.5f * w * z4 + 5.625f * w2 * z2 - 0.3125f * w3);

    // m = 1
    {
        const float P21 = 2.f * z;
        const float P31 = 3.f * z2 - 0.75f * w;
        const float P41 = z * (4.f * z2 - 3.f * w);
        const float P51 = 5.f * z4 - 7.5f * w * z2 + 0.625f * w2;
        const float P61 = z * (6.f * z4 - 15.f * w * z2 + 3.75f * w2);
        o[1]  = sns[1]  * y;
        o[3]  = sns[3]  * x;
        o[5]  = sns[5]  * (P21 * y);
        o[7]  = sns[7]  * (P21 * x);
        o[11] = sns[11] * (P31 * y);
        o[13] = sns[13] * (P31 * x);
        o[19] = sns[19] * (P41 * y);
        o[21] = sns[21] * (P41 * x);
        o[29] = sns[29] * (P51 * y);
        o[31] = sns[31] * (P51 * x);
        o[41] = sns[41] * (P61 * y);
        o[43] = sns[43] * (P61 * x);
    }

    // m = 2
    const float A2 = x * x - y * y;
    const float B2 = 2.f * x * y;
    {
        const float P32 = 3.f * z;
        const float P42 = 6.f * z2 - w;
        const float P52 = z * (10.f * z2 - 5.f * w);
        const float P62 = 15.f * z4 - 15.f * w * z2 + 0.9375f * w2;
        o[4]  = sns[4]  * B2;
        o[8]  = sns[8]  * A2;
        o[10] = sns[10] * (P32 * B2);
        o[14] = sns[14] * (P32 * A2);
        o[18] = sns[18] * (P42 * B2);
        o[22] = sns[22] * (P42 * A2);
        o[28] = sns[28] * (P52 * B2);
        o[32] = sns[32] * (P52 * A2);
        o[40] = sns[40] * (P62 * B2);
        o[44] = sns[44] * (P62 * A2);
    }

    // m = 3
    const float A3 = x * A2 - y * B2;
    const float B3 = x * B2 + y * A2;
    {
        const float P43 = 4.f * z;
        const float P53 = 10.f * z2 - 1.25f * w;
        const float P63 = z * (20.f * z2 - 7.5f * w);
        o[9]  = sns[9]  * B3;
        o[15] = sns[15] * A3;
        o[17] = sns[17] * (P43 * B3);
        o[23] = sns[23] * (P43 * A3);
        o[27] = sns[27] * (P53 * B3);
        o[33] = sns[33] * (P53 * A3);
        o[39] = sns[39] * (P63 * B3);
        o[45] = sns[45] * (P63 * A3);
    }

    // m = 4
    const float A4 = x * A3 - y * B3;
    const float B4 = x * B3 + y * A3;
    {
        const float P54 = 5.f * z;
        const float P64 = 15.f * z2 - 1.5f * w;
        o[16] = sns[16] * B4;
        o[24] = sns[24] * A4;
        o[26] = sns[26] * (P54 * B4);
        o[34] = sns[34] * (P54 * A4);
        o[38] = sns[38] * (P64 * B4);
        o[46] = sns[46] * (P64 * A4);
    }

    // m = 5
    const float A5 = x * A4 - y * B4;
    const float B5 = x * B4 + y * A4;
    {
        const float P65 = 6.f * z;
        o[25] = sns[25] * B5;
        o[35] = sns[35] * A5;
        o[37] = sns[37] * (P65 * B5);
        o[47] = sns[47] * (P65 * A5);
    }

    // m = 6
    o[36] = sns[36] * (x * B5 + y * A5);
    o[48] = sns[48] * (x * A5 - y * B5);
}

__global__ __launch_bounds__(BLK) void rsh_kernel(
    const float* __restrict__ xyz,
    const float* __restrict__ ns,
    float* __restrict__ out,
    int N)
{
    extern __shared__ float sh[];      // TILE_FLOATS
    __shared__ float sns[NOUT];

    const int tid = threadIdx.x;
    const int base = blockIdx.x * BLK;
    const int pt = base + tid;

    if (tid < NOUT) sns[tid] = ns[tid];

    float x = 0.f, y = 0.f, z = 0.f;
    if (pt < N) {
        x = __ldg(&xyz[(size_t)pt * 3 + 0]);
        y = __ldg(&xyz[(size_t)pt * 3 + 1]);
        z = __ldg(&xyz[(size_t)pt * 3 + 2]);
    }
    __syncthreads();   // sns visible

    if (pt < N)
        compute_point(x, y, z, sns, sh + tid * NOUT);
    __syncthreads();   // all STS done

    const int npts = min(N - base, BLK);
    if (npts == BLK) {
        if (tid == 0) {
            asm volatile("fence.proxy.async.shared::cta;" ::: "memory");
            const uint64_t dst = (uint64_t)(uintptr_t)(out + (size_t)base * NOUT);
            const uint32_t src = smem_u32(sh);
            asm volatile(
                "cp.async.bulk.global.shared::cta.bulk_group [%0], [%1], %2;"
                :: "l"(dst), "r"(src), "r"((uint32_t)TILE_BYTES) : "memory");
            asm volatile("cp.async.bulk.commit_group;" ::: "memory");
            // keep CTA (and its smem) alive until the bulk read completes;
            // all other threads exit immediately and free their warp slots
            asm volatile("cp.async.bulk.wait_group 0;" ::: "memory");
        }
    } else if (npts > 0) {
        // tail block: scalar coalesced flush
        const int total = npts * NOUT;
        const size_t ob = (size_t)base * NOUT;
        for (int i = tid; i < total; i += BLK) out[ob + i] = sh[i];
    }
}

extern "C" void kernel_launch(void* const* d_in, const int* in_sizes, int n_in,
                              void* d_out, int out_size)
{
    const float* xyz = (const float*)d_in[0];   // [N, 3] f32
    const float* ns  = (const float*)d_in[2];   // [49] f32 (ns_lms)
    float* out = (float*)d_out;                 // [N, 49] f32
    const int N = in_sizes[0] / 3;

    static bool attr_set = false;
    if (!attr_set) {
        cudaFuncSetAttribute(rsh_kernel,
                             cudaFuncAttributeMaxDynamicSharedMemorySize,
                             TILE_BYTES);
        attr_set = true;
    }

    const int grid = (N + BLK - 1) / BLK;
    rsh_kernel<<<grid, BLK, TILE_BYTES>>>(xyz, ns, out, N);
}

// round 9
// speedup vs baseline: 1.3516x; 1.3516x over previous
#include <cuda_runtime.h>
#include <cstdint>

// Real solid harmonics, max_l = 6, factored form:
//   out[l(l+1)+m] = ns[l(l+1)+m] * P_{l,|m|}(z, w) * (A_|m| or B_|m|)
// with w = x^2+y^2, A_m + i B_m = (x + i y)^m.
// Small-CTA design: 64 points per CTA staged in 12.5KB static smem, one TMA
// bulk store, CTA retires as soon as the drain completes. Many small CTAs
// per SM overlap drain of retiring CTAs with compute of fresh ones.

#define BLK 64
#define NOUT 49
#define TILE_FLOATS (BLK * NOUT)
#define TILE_BYTES (TILE_FLOATS * 4)   // 12544, multiple of 16

__device__ __forceinline__ uint32_t smem_u32(const void* p) {
    uint32_t a;
    asm("{ .reg .u64 t; cvta.to.shared.u64 t, %1; cvt.u32.u64 %0, t; }"
        : "=r"(a) : "l"(p));
    return a;
}

__device__ __forceinline__ void compute_point(
    float x, float y, float z, const float* __restrict__ sns, float* __restrict__ o)
{
    const float w  = x * x + y * y;
    const float z2 = z * z;
    const float z4 = z2 * z2;
    const float z6 = z4 * z2;
    const float w2 = w * w;
    const float w3 = w2 * w;

    // m = 0
    o[0]  = sns[0];
    o[2]  = sns[2]  * z;
    o[6]  = sns[6]  * (z2 - 0.5f * w);
    o[12] = sns[12] * (z * (z2 - 1.5f * w));
    o[20] = sns[20] * (z4 - 3.f * w * z2 + 0.375f * w2);
    o[30] = sns[30] * (z * (z4 - 5.f * w * z2 + 1.875f * w2));
    o[42] = sns[42] * (z6 - 7.5f * w * z4 + 5.625f * w2 * z2 - 0.3125f * w3);

    // m = 1
    {
        const float P21 = 2.f * z;
        const float P31 = 3.f * z2 - 0.75f * w;
        const float P41 = z * (4.f * z2 - 3.f * w);
        const float P51 = 5.f * z4 - 7.5f * w * z2 + 0.625f * w2;
        const float P61 = z * (6.f * z4 - 15.f * w * z2 + 3.75f * w2);
        o[1]  = sns[1]  * y;
        o[3]  = sns[3]  * x;
        o[5]  = sns[5]  * (P21 * y);
        o[7]  = sns[7]  * (P21 * x);
        o[11] = sns[11] * (P31 * y);
        o[13] = sns[13] * (P31 * x);
        o[19] = sns[19] * (P41 * y);
        o[21] = sns[21] * (P41 * x);
        o[29] = sns[29] * (P51 * y);
        o[31] = sns[31] * (P51 * x);
        o[41] = sns[41] * (P61 * y);
        o[43] = sns[43] * (P61 * x);
    }

    // m = 2
    const float A2 = x * x - y * y;
    const float B2 = 2.f * x * y;
    {
        const float P32 = 3.f * z;
        const float P42 = 6.f * z2 - w;
        const float P52 = z * (10.f * z2 - 5.f * w);
        const float P62 = 15.f * z4 - 15.f * w * z2 + 0.9375f * w2;
        o[4]  = sns[4]  * B2;
        o[8]  = sns[8]  * A2;
        o[10] = sns[10] * (P32 * B2);
        o[14] = sns[14] * (P32 * A2);
        o[18] = sns[18] * (P42 * B2);
        o[22] = sns[22] * (P42 * A2);
        o[28] = sns[28] * (P52 * B2);
        o[32] = sns[32] * (P52 * A2);
        o[40] = sns[40] * (P62 * B2);
        o[44] = sns[44] * (P62 * A2);
    }

    // m = 3
    const float A3 = x * A2 - y * B2;
    const float B3 = x * B2 + y * A2;
    {
        const float P43 = 4.f * z;
        const float P53 = 10.f * z2 - 1.25f * w;
        const float P63 = z * (20.f * z2 - 7.5f * w);
        o[9]  = sns[9]  * B3;
        o[15] = sns[15] * A3;
        o[17] = sns[17] * (P43 * B3);
        o[23] = sns[23] * (P43 * A3);
        o[27] = sns[27] * (P53 * B3);
        o[33] = sns[33] * (P53 * A3);
        o[39] = sns[39] * (P63 * B3);
        o[45] = sns[45] * (P63 * A3);
    }

    // m = 4
    const float A4 = x * A3 - y * B3;
    const float B4 = x * B3 + y * A3;
    {
        const float P54 = 5.f * z;
        const float P64 = 15.f * z2 - 1.5f * w;
        o[16] = sns[16] * B4;
        o[24] = sns[24] * A4;
        o[26] = sns[26] * (P54 * B4);
        o[34] = sns[34] * (P54 * A4);
        o[38] = sns[38] * (P64 * B4);
        o[46] = sns[46] * (P64 * A4);
    }

    // m = 5
    const float A5 = x * A4 - y * B4;
    const float B5 = x * B4 + y * A4;
    {
        const float P65 = 6.f * z;
        o[25] = sns[25] * B5;
        o[35] = sns[35] * A5;
        o[37] = sns[37] * (P65 * B5);
        o[47] = sns[47] * (P65 * A5);
    }

    // m = 6
    o[36] = sns[36] * (x * B5 + y * A5);
    o[48] = sns[48] * (x * A5 - y * B5);
}

__global__ __launch_bounds__(BLK) void rsh_kernel(
    const float* __restrict__ xyz,
    const float* __restrict__ ns,
    float* __restrict__ out,
    int N)
{
    __shared__ float sh[TILE_FLOATS];   // 12544 B staging
    __shared__ float sns[NOUT];

    const int tid = threadIdx.x;
    const int base = blockIdx.x * BLK;
    const int pt = base + tid;

    if (tid < NOUT) sns[tid] = ns[tid];

    float x = 0.f, y = 0.f, z = 0.f;
    if (pt < N) {
        x = __ldg(&xyz[(size_t)pt * 3 + 0]);
        y = __ldg(&xyz[(size_t)pt * 3 + 1]);
        z = __ldg(&xyz[(size_t)pt * 3 + 2]);
    }
    __syncthreads();   // sns visible

    if (pt < N)
        compute_point(x, y, z, sns, sh + tid * NOUT);
    __syncthreads();   // all STS done

    const int npts = min(N - base, BLK);
    if (npts == BLK) {
        if (tid == 0) {
            asm volatile("fence.proxy.async.shared::cta;" ::: "memory");
            const uint64_t dst = (uint64_t)(uintptr_t)(out + (size_t)base * NOUT);
            const uint32_t src = smem_u32(sh);
            asm volatile(
                "cp.async.bulk.global.shared::cta.bulk_group [%0], [%1], %2;"
                :: "l"(dst), "r"(src), "r"((uint32_t)TILE_BYTES) : "memory");
            asm volatile("cp.async.bulk.commit_group;" ::: "memory");
            // hold the CTA (and its smem) until the bulk read completes;
            // the other warp exits immediately
            asm volatile("cp.async.bulk.wait_group 0;" ::: "memory");
        }
    } else if (npts > 0) {
        // tail block: scalar coalesced flush
        const int total = npts * NOUT;
        const size_t ob = (size_t)base * NOUT;
        for (int i = tid; i < total; i += BLK) out[ob + i] = sh[i];
    }
}

extern "C" void kernel_launch(void* const* d_in, const int* in_sizes, int n_in,
                              void* d_out, int out_size)
{
    const float* xyz = (const float*)d_in[0];   // [N, 3] f32
    const float* ns  = (const float*)d_in[2];   // [49] f32 (ns_lms)
    float* out = (float*)d_out;                 // [N, 49] f32
    const int N = in_sizes[0] / 3;

    const int grid = (N + BLK - 1) / BLK;
    rsh_kernel<<<grid, BLK>>>(xyz, ns, out, N);
}

// round 11
// speedup vs baseline: 1.3741x; 1.0166x over previous
#include <cuda_runtime.h>
#include <cstdint>

// Real solid harmonics, max_l = 6, factored form:
//   out[l(l+1)+m] = ns[l(l+1)+m] * P_{l,|m|}(z, w) * (A_|m| or B_|m|)
// with w = x^2+y^2, A_m + i B_m = (x + i y)^m.
// Warp-autonomous staging: each warp stages 32x49 f32 (6272B) in its own smem
// slice and fires its own TMA bulk store guarded by __syncwarp + async fence.
// wait_group.read (not wait_group) -> CTA retires as soon as smem is re-read,
// without waiting for the global-write round trip.

#define BLK 128
#define WARPS (BLK / 32)
#define NOUT 49
#define WTILE_FLOATS (32 * NOUT)
#define WTILE_BYTES (WTILE_FLOATS * 4)   // 6272, multiple of 16

__device__ __forceinline__ uint32_t smem_u32(const void* p) {
    uint32_t a;
    asm("{ .reg .u64 t; cvta.to.shared.u64 t, %1; cvt.u32.u64 %0, t; }"
        : "=r"(a) : "l"(p));
    return a;
}

__device__ __forceinline__ void compute_point(
    float x, float y, float z, const float* __restrict__ sns, float* __restrict__ o)
{
    const float w  = x * x + y * y;
    const float z2 = z * z;
    const float z4 = z2 * z2;
    const float z6 = z4 * z2;
    const float w2 = w * w;
    const float w3 = w2 * w;

    // m = 0
    o[0]  = sns[0];
    o[2]  = sns[2]  * z;
    o[6]  = sns[6]  * (z2 - 0.5f * w);
    o[12] = sns[12] * (z * (z2 - 1.5f * w));
    o[20] = sns[20] * (z4 - 3.f * w * z2 + 0.375f * w2);
    o[30] = sns[30] * (z * (z4 - 5.f * w * z2 + 1.875f * w2));
    o[42] = sns[42] * (z6 - 7.5f * w * z4 + 5.625f * w2 * z2 - 0.3125f * w3);

    // m = 1
    {
        const float P21 = 2.f * z;
        const float P31 = 3.f * z2 - 0.75f * w;
        const float P41 = z * (4.f * z2 - 3.f * w);
        const float P51 = 5.f * z4 - 7.5f * w * z2 + 0.625f * w2;
        const float P61 = z * (6.f * z4 - 15.f * w * z2 + 3.75f * w2);
        o[1]  = sns[1]  * y;
        o[3]  = sns[3]  * x;
        o[5]  = sns[5]  * (P21 * y);
        o[7]  = sns[7]  * (P21 * x);
        o[11] = sns[11] * (P31 * y);
        o[13] = sns[13] * (P31 * x);
        o[19] = sns[19] * (P41 * y);
        o[21] = sns[21] * (P41 * x);
        o[29] = sns[29] * (P51 * y);
        o[31] = sns[31] * (P51 * x);
        o[41] = sns[41] * (P61 * y);
        o[43] = sns[43] * (P61 * x);
    }

    // m = 2
    const float A2 = x * x - y * y;
    const float B2 = 2.f * x * y;
    {
        const float P32 = 3.f * z;
        const float P42 = 6.f * z2 - w;
        const float P52 = z * (10.f * z2 - 5.f * w);
        const float P62 = 15.f * z4 - 15.f * w * z2 + 0.9375f * w2;
        o[4]  = sns[4]  * B2;
        o[8]  = sns[8]  * A2;
        o[10] = sns[10] * (P32 * B2);
        o[14] = sns[14] * (P32 * A2);
        o[18] = sns[18] * (P42 * B2);
        o[22] = sns[22] * (P42 * A2);
        o[28] = sns[28] * (P52 * B2);
        o[32] = sns[32] * (P52 * A2);
        o[40] = sns[40] * (P62 * B2);
        o[44] = sns[44] * (P62 * A2);
    }

    // m = 3
    const float A3 = x * A2 - y * B2;
    const float B3 = x * B2 + y * A2;
    {
        const float P43 = 4.f * z;
        const float P53 = 10.f * z2 - 1.25f * w;
        const float P63 = z * (20.f * z2 - 7.5f * w);
        o[9]  = sns[9]  * B3;
        o[15] = sns[15] * A3;
        o[17] = sns[17] * (P43 * B3);
        o[23] = sns[23] * (P43 * A3);
        o[27] = sns[27] * (P53 * B3);
        o[33] = sns[33] * (P53 * A3);
        o[39] = sns[39] * (P63 * B3);
        o[45] = sns[45] * (P63 * A3);
    }

    // m = 4
    const float A4 = x * A3 - y * B3;
    const float B4 = x * B3 + y * A3;
    {
        const float P54 = 5.f * z;
        const float P64 = 15.f * z2 - 1.5f * w;
        o[16] = sns[16] * B4;
        o[24] = sns[24] * A4;
        o[26] = sns[26] * (P54 * B4);
        o[34] = sns[34] * (P54 * A4);
        o[38] = sns[38] * (P64 * B4);
        o[46] = sns[46] * (P64 * A4);
    }

    // m = 5
    const float A5 = x * A4 - y * B4;
    const float B5 = x * B4 + y * A4;
    {
        const float P65 = 6.f * z;
        o[25] = sns[25] * B5;
        o[35] = sns[35] * A5;
        o[37] = sns[37] * (P65 * B5);
        o[47] = sns[47] * (P65 * A5);
    }

    // m = 6
    o[36] = sns[36] * (x * B5 + y * A5);
    o[48] = sns[48] * (x * A5 - y * B5);
}

__global__ __launch_bounds__(BLK) void rsh_kernel(
    const float* __restrict__ xyz,
    const float* __restrict__ ns,
    float* __restrict__ out,
    int N)
{
    __shared__ float sh[WARPS * WTILE_FLOATS];   // 25088 B staging
    __shared__ float sns[NOUT];

    const int tid = threadIdx.x;
    const int wid = tid >> 5;
    const int lid = tid & 31;
    const int wbase = blockIdx.x * BLK + wid * 32;   // this warp's first point
    const int pt = wbase + lid;

    if (tid < NOUT) sns[tid] = ns[tid];

    float x = 0.f, y = 0.f, z = 0.f;
    if (pt < N) {
        x = __ldg(&xyz[(size_t)pt * 3 + 0]);
        y = __ldg(&xyz[(size_t)pt * 3 + 1]);
        z = __ldg(&xyz[(size_t)pt * 3 + 2]);
    }
    __syncthreads();   // sns visible to all warps

    float* wbuf = sh + wid * WTILE_FLOATS;
    if (pt < N)
        compute_point(x, y, z, sns, wbuf + lid * NOUT);

    const int npts = min(N - wbase, 32);
    if (npts == 32) {
        // warp-autonomous TMA drain of this warp's 6272B slice
        __syncwarp();
        asm volatile("fence.proxy.async.shared::cta;" ::: "memory");  // all lanes
        __syncwarp();
        if (lid == 0) {
            const uint64_t dst = (uint64_t)(uintptr_t)(out + (size_t)wbase * NOUT);
            const uint32_t src = smem_u32(wbuf);
            asm volatile(
                "cp.async.bulk.global.shared::cta.bulk_group [%0], [%1], %2;"
                :: "l"(dst), "r"(src), "r"((uint32_t)WTILE_BYTES) : "memory");
            asm volatile("cp.async.bulk.commit_group;" ::: "memory");
            // wait only until the smem tile has been READ (safe to retire CTA);
            // do not wait for the global write round-trip
            asm volatile("cp.async.bulk.wait_group.read 0;" ::: "memory");
        }
    } else if (npts > 0) {
        // tail warp: scalar coalesced-ish flush of npts*49 floats
        __syncwarp();
        const int total = npts * NOUT;
        const size_t ob = (size_t)wbase * NOUT;
        for (int i = lid; i < total; i += 32) out[ob + i] = wbuf[i];
    }
}

extern "C" void kernel_launch(void* const* d_in, const int* in_sizes, int n_in,
                              void* d_out, int out_size)
{
    const float* xyz = (const float*)d_in[0];   // [N, 3] f32
    const float* ns  = (const float*)d_in[2];   // [49] f32 (ns_lms)
    float* out = (float*)d_out;                 // [N, 49] f32
    const int N = in_sizes[0] / 3;

    const int grid = (N + BLK - 1) / BLK;
    rsh_kernel<<<grid, BLK>>>(xyz, ns, out, N);
}